// round 11
// baseline (speedup 1.0000x reference)
#include <cuda_runtime.h>
#include <math.h>

#define D   256
#define NQ  512
#define NK  512

// ---------------- scratch ----------------
__device__ __align__(16) float g_aq[D * NQ];      // (d, n)
__device__ __align__(16) float g_ak[D * NK];      // (d, m)
__device__ __align__(16) float g_probT[NK * NQ];  // (m, n)
__device__ __align__(16) float g_msg[D * NQ];     // (d, n)
__device__ __align__(16) float g_h2[2 * D * NQ];  // (o, n)

// ---------------- tf32 helpers ----------------
__device__ __forceinline__ float f2tf(float f) {
    unsigned u; asm("cvt.rna.tf32.f32 %0, %1;" : "=r"(u) : "f"(f));
    return __uint_as_float(u);
}
__device__ __forceinline__ void mma_tf32(float4& c,
    float a0, float a1, float a2, float a3, float b0, float b1)
{
    asm("mma.sync.aligned.m16n8k8.row.col.f32.tf32.tf32.f32 "
        "{%0,%1,%2,%3}, {%4,%5,%6,%7}, {%8,%9}, {%0,%1,%2,%3};"
        : "+f"(c.x), "+f"(c.y), "+f"(c.z), "+f"(c.w)
        : "r"(__float_as_uint(a0)), "r"(__float_as_uint(a1)),
          "r"(__float_as_uint(a2)), "r"(__float_as_uint(a3)),
          "r"(__float_as_uint(b0)), "r"(__float_as_uint(b1)));
}

// ---------- TF32 MMA GEMM, tile 32 x 64, 256 thr, 2-way split-K (r10 core) --
template<bool DUAL>
__device__ __forceinline__ void gemm_mma(
    const float* __restrict__ W, const float* __restrict__ X0,
    const float* __restrict__ X1, const float* __restrict__ bias,
    float* __restrict__ out, int K, bool relu)
{
    const int n0   = blockIdx.x * 64;
    const int o0   = blockIdx.y * 32;
    const int tid  = threadIdx.x;      // 256
    const int wg   = tid >> 7;         // K half
    const int t    = tid & 127;
    const int wq   = t >> 5;           // warp within wg
    const int lane = t & 31;
    const int g    = lane >> 2, t4 = lane & 3;
    const int mt   = wq & 1;           // m16 tile (0/1)
    const int ng   = (wq >> 1) * 32;   // n group (0/32)

    __shared__ __align__(16) float sW[2][32 * 40];  // [k][o]
    __shared__ __align__(16) float sX[2][32 * 72];  // [k][n]
    __shared__ __align__(16) float sR[4][32][16];

    const int wo  = t >> 2, wf = t & 3;
    const int xn4 = t & 15, xkr = t >> 4;

    const int kb  = wg * (K >> 1);
    const int NIT = K >> 6;

    float4 rw[2], rx[4];
    float4 acc[4];
    #pragma unroll
    for (int j = 0; j < 4; j++) acc[j] = make_float4(0.f, 0.f, 0.f, 0.f);

    {
        const int k0 = kb;
        #pragma unroll
        for (int p = 0; p < 2; p++)
            rw[p] = *(const float4*)&W[(o0 + wo) * 512 + k0 + (wf + p * 4) * 4];
        const float* Xb = (!DUAL || k0 < 256) ? X0 + k0 * 512
                                              : X1 + (k0 - 256) * 512;
        #pragma unroll
        for (int p = 0; p < 4; p++)
            rx[p] = *(const float4*)&Xb[(xkr + p * 8) * 512 + n0 + xn4 * 4];
    }

    for (int it = 0; it < NIT; it++) {
        __syncthreads();
        #pragma unroll
        for (int p = 0; p < 2; p++) {
            const int kB = (wf + p * 4) * 4;
            sW[wg][(kB + 0) * 40 + wo] = f2tf(rw[p].x);
            sW[wg][(kB + 1) * 40 + wo] = f2tf(rw[p].y);
            sW[wg][(kB + 2) * 40 + wo] = f2tf(rw[p].z);
            sW[wg][(kB + 3) * 40 + wo] = f2tf(rw[p].w);
        }
        #pragma unroll
        for (int p = 0; p < 4; p++) {
            float4 c = make_float4(f2tf(rx[p].x), f2tf(rx[p].y),
                                   f2tf(rx[p].z), f2tf(rx[p].w));
            *(float4*)&sX[wg][(xkr + p * 8) * 72 + xn4 * 4] = c;
        }
        __syncthreads();

        if (it + 1 < NIT) {
            const int k0 = kb + (it + 1) * 32;
            #pragma unroll
            for (int p = 0; p < 2; p++)
                rw[p] = *(const float4*)&W[(o0 + wo) * 512 + k0 + (wf + p * 4) * 4];
            const float* Xb = (!DUAL || k0 < 256) ? X0 + k0 * 512
                                                  : X1 + (k0 - 256) * 512;
            #pragma unroll
            for (int p = 0; p < 4; p++)
                rx[p] = *(const float4*)&Xb[(xkr + p * 8) * 512 + n0 + xn4 * 4];
        }

        #pragma unroll
        for (int s = 0; s < 4; s++) {
            const int ks = s * 8;
            const int ob = mt * 16 + g;
            float a0 = sW[wg][(ks + t4) * 40 + ob];
            float a1 = sW[wg][(ks + t4) * 40 + ob + 8];
            float a2 = sW[wg][(ks + t4 + 4) * 40 + ob];
            float a3 = sW[wg][(ks + t4 + 4) * 40 + ob + 8];
            #pragma unroll
            for (int j = 0; j < 4; j++) {
                const int nc = ng + j * 8 + g;
                float b0 = sX[wg][(ks + t4) * 72 + nc];
                float b1 = sX[wg][(ks + t4 + 4) * 72 + nc];
                mma_tf32(acc[j], a0, a1, a2, a3, b0, b1);
            }
        }
    }

    if (wg == 1) {
        #pragma unroll
        for (int j = 0; j < 4; j++) *(float4*)&sR[wq][lane][j * 4] = acc[j];
    }
    __syncthreads();
    if (wg == 0) {
        const int oA = o0 + mt * 16 + g;
        const int oB = oA + 8;
        const float bA = bias ? bias[oA] : 0.f;
        const float bB = bias ? bias[oB] : 0.f;
        #pragma unroll
        for (int j = 0; j < 4; j++) {
            float4 r = *(const float4*)&sR[wq][lane][j * 4];
            float c0 = acc[j].x + r.x + bA;
            float c1 = acc[j].y + r.y + bA;
            float c2 = acc[j].z + r.z + bB;
            float c3 = acc[j].w + r.w + bB;
            if (relu) {
                c0 = fmaxf(c0, 0.f); c1 = fmaxf(c1, 0.f);
                c2 = fmaxf(c2, 0.f); c3 = fmaxf(c3, 0.f);
            }
            const int nc = n0 + ng + j * 8 + 2 * t4;
            *(float2*)&out[oA * 512 + nc] = make_float2(c0, c1);
            *(float2*)&out[oB * 512 + nc] = make_float2(c2, c3);
        }
    }
}

// ---------- TF32 MMA GEMM, tile 16 x 64, 256 thr, 4-way split-K ------------
// For 256-row outputs (grid (8,16) = 128 blocks). 4 warpgroups x 2 warps;
// each warp computes m16 x n32 (wq selects n half). KC=16.
__device__ __forceinline__ void gemm_mma16(
    const float* __restrict__ W, const float* __restrict__ X0,
    const float* __restrict__ bias, float* __restrict__ out, int K)
{
    const int n0   = blockIdx.x * 64;
    const int o0   = blockIdx.y * 16;
    const int tid  = threadIdx.x;        // 256
    const int warp = tid >> 5;
    const int lane = tid & 31;
    const int wg   = warp >> 1;          // 0..3 K quarter
    const int wq   = warp & 1;           // n half
    const int g    = lane >> 2, t4 = lane & 3;

    __shared__ __align__(16) float sW[4][16 * 24];  // [k][o]
    __shared__ __align__(16) float sX[4][16 * 72];  // [k][n]
    __shared__ __align__(16) float sR[3][2][32][16];

    const int t2  = tid & 63;
    const int wf  = t2 >> 4;             // k f4 (0..3)
    const int wo  = t2 & 15;             // o row
    const int xn4 = t2 & 15, xkr = t2 >> 4;

    const int kb  = wg * (K >> 2);
    const int NIT = K >> 6;              // (K/4)/16

    float4 rw, rx[4];
    float4 acc[4];
    #pragma unroll
    for (int j = 0; j < 4; j++) acc[j] = make_float4(0.f, 0.f, 0.f, 0.f);

    rw = *(const float4*)&W[(o0 + wo) * 512 + kb + wf * 4];
    #pragma unroll
    for (int p = 0; p < 4; p++)
        rx[p] = *(const float4*)&X0[(kb + xkr + p * 4) * 512 + n0 + xn4 * 4];

    for (int it = 0; it < NIT; it++) {
        __syncthreads();
        {
            const int kB = wf * 4;
            sW[wg][(kB + 0) * 24 + wo] = f2tf(rw.x);
            sW[wg][(kB + 1) * 24 + wo] = f2tf(rw.y);
            sW[wg][(kB + 2) * 24 + wo] = f2tf(rw.z);
            sW[wg][(kB + 3) * 24 + wo] = f2tf(rw.w);
        }
        #pragma unroll
        for (int p = 0; p < 4; p++) {
            float4 c = make_float4(f2tf(rx[p].x), f2tf(rx[p].y),
                                   f2tf(rx[p].z), f2tf(rx[p].w));
            *(float4*)&sX[wg][(xkr + p * 4) * 72 + xn4 * 4] = c;
        }
        __syncthreads();

        if (it + 1 < NIT) {
            const int k0 = kb + (it + 1) * 16;
            rw = *(const float4*)&W[(o0 + wo) * 512 + k0 + wf * 4];
            #pragma unroll
            for (int p = 0; p < 4; p++)
                rx[p] = *(const float4*)&X0[(k0 + xkr + p * 4) * 512 + n0 + xn4 * 4];
        }

        #pragma unroll
        for (int s = 0; s < 2; s++) {
            const int ks = s * 8;
            float a0 = sW[wg][(ks + t4) * 24 + g];
            float a1 = sW[wg][(ks + t4) * 24 + g + 8];
            float a2 = sW[wg][(ks + t4 + 4) * 24 + g];
            float a3 = sW[wg][(ks + t4 + 4) * 24 + g + 8];
            #pragma unroll
            for (int j = 0; j < 4; j++) {
                const int nc = wq * 32 + j * 8 + g;
                float b0 = sX[wg][(ks + t4) * 72 + nc];
                float b1 = sX[wg][(ks + t4 + 4) * 72 + nc];
                mma_tf32(acc[j], a0, a1, a2, a3, b0, b1);
            }
        }
    }

    if (wg >= 1) {
        #pragma unroll
        for (int j = 0; j < 4; j++)
            *(float4*)&sR[wg - 1][wq][lane][j * 4] = acc[j];
    }
    __syncthreads();
    if (wg == 0) {
        const int oA = o0 + g;
        const int oB = oA + 8;
        const float bA = bias ? bias[oA] : 0.f;
        const float bB = bias ? bias[oB] : 0.f;
        #pragma unroll
        for (int j = 0; j < 4; j++) {
            float4 r1 = *(const float4*)&sR[0][wq][lane][j * 4];
            float4 r2 = *(const float4*)&sR[1][wq][lane][j * 4];
            float4 r3 = *(const float4*)&sR[2][wq][lane][j * 4];
            float c0 = acc[j].x + r1.x + r2.x + r3.x + bA;
            float c1 = acc[j].y + r1.y + r2.y + r3.y + bA;
            float c2 = acc[j].z + r1.z + r2.z + r3.z + bB;
            float c3 = acc[j].w + r1.w + r2.w + r3.w + bB;
            const int nc = n0 + wq * 32 + j * 8 + 2 * t4;
            *(float2*)&out[oA * 512 + nc] = make_float2(c0, c1);
            *(float2*)&out[oB * 512 + nc] = make_float2(c2, c3);
        }
    }
}

// ---------------- stage kernels ----------------

// aq = w1[:, :D] @ x + b1 ; ak = w1[:, D:] @ src   grid (8,8,2), 256 thr
__global__ void __launch_bounds__(256) k_qk(
    const float* __restrict__ w1, const float* __restrict__ x,
    const float* __restrict__ src, const float* __restrict__ b1)
{
    if (blockIdx.z == 0)
        gemm_mma<false>(w1,       x,   nullptr, b1,      g_aq, 256, false);
    else
        gemm_mma<false>(w1 + 256, src, nullptr, nullptr, g_ak, 256, false);
}

// scores[n][m] = sum_d w2[d]*relu(aq[d][n]+ak[d][m]) + b2   grid (8,16), 256 thr
__global__ void __launch_bounds__(256) k_score(
    const float* __restrict__ w2, const float* __restrict__ b2,
    float* __restrict__ scores)
{
    const int m0  = blockIdx.x * 64;
    const int n0  = blockIdx.y * 32;
    const int tid = threadIdx.x;
    const int wg  = tid >> 7;
    const int t   = tid & 127;
    const int mI  = t & 15;
    const int nG  = t >> 4;

    __shared__ __align__(16) float sA[2][32 * 36];
    __shared__ __align__(16) float sB[2][32 * 68];
    __shared__ float sw[2][32];
    __shared__ __align__(16) float sR[128 * 16];

    const int an4 = t & 7,  adr = t >> 3;
    const int bm4 = t & 15, bdr = t >> 4;
    const int db  = wg * 128;

    float4 ra[2], rb[4];
    float rwv;
    float4 acc[4];
    #pragma unroll
    for (int j = 0; j < 4; j++) acc[j] = make_float4(0.f, 0.f, 0.f, 0.f);

    #pragma unroll
    for (int p = 0; p < 2; p++)
        ra[p] = *(const float4*)&g_aq[(db + adr + p * 16) * 512 + n0 + an4 * 4];
    #pragma unroll
    for (int p = 0; p < 4; p++)
        rb[p] = *(const float4*)&g_ak[(db + bdr + p * 8) * 512 + m0 + bm4 * 4];
    rwv = (t < 32) ? w2[db + t] : 0.f;

    for (int it = 0; it < 4; it++) {
        __syncthreads();
        #pragma unroll
        for (int p = 0; p < 2; p++)
            *(float4*)&sA[wg][(adr + p * 16) * 36 + an4 * 4] = ra[p];
        #pragma unroll
        for (int p = 0; p < 4; p++)
            *(float4*)&sB[wg][(bdr + p * 8) * 68 + bm4 * 4] = rb[p];
        if (t < 32) sw[wg][t] = rwv;
        __syncthreads();

        if (it + 1 < 4) {
            const int d0 = db + (it + 1) * 32;
            #pragma unroll
            for (int p = 0; p < 2; p++)
                ra[p] = *(const float4*)&g_aq[(d0 + adr + p * 16) * 512 + n0 + an4 * 4];
            #pragma unroll
            for (int p = 0; p < 4; p++)
                rb[p] = *(const float4*)&g_ak[(d0 + bdr + p * 8) * 512 + m0 + bm4 * 4];
            if (t < 32) rwv = w2[d0 + t];
        }

        #pragma unroll
        for (int d = 0; d < 32; d++) {
            float4 av = *(const float4*)&sA[wg][d * 36 + nG * 4];
            float4 bv = *(const float4*)&sB[wg][d * 68 + mI * 4];
            float w  = sw[wg][d];
            float a[4] = {av.x, av.y, av.z, av.w};
            #pragma unroll
            for (int j = 0; j < 4; j++) {
                acc[j].x += w * fmaxf(a[j] + bv.x, 0.f);
                acc[j].y += w * fmaxf(a[j] + bv.y, 0.f);
                acc[j].z += w * fmaxf(a[j] + bv.z, 0.f);
                acc[j].w += w * fmaxf(a[j] + bv.w, 0.f);
            }
        }
    }

    if (wg == 1) {
        #pragma unroll
        for (int j = 0; j < 4; j++)
            *(float4*)&sR[(t * 4 + j) * 4] = acc[j];
    }
    __syncthreads();
    if (wg == 0) {
        const float bs = b2[0];
        #pragma unroll
        for (int j = 0; j < 4; j++) {
            float4 r = *(const float4*)&sR[(t * 4 + j) * 4];
            const int n = n0 + nG * 4 + j;
            float4 v = acc[j];
            v.x += r.x + bs; v.y += r.y + bs;
            v.z += r.z + bs; v.w += r.w + bs;
            *(float4*)&scores[n * 512 + m0 + mI * 4] = v;
        }
    }
}

// softmax over m per row n -> transposed prob. 128 blocks x 256 thr.
__global__ void __launch_bounds__(256) k_softmaxT(const float* __restrict__ scores)
{
    const int n0   = blockIdx.x * 4;
    const int tid  = threadIdx.x;
    const int w    = tid >> 5, lane = tid & 31;
    const int r    = w >> 1, h = w & 1;
    __shared__ float sP[4][516];
    __shared__ float sred[8];

    const float* row = scores + (n0 + r) * 512 + h * 256;
    float v[8];
    float mx = -1e30f;
    #pragma unroll
    for (int i = 0; i < 8; i++) { v[i] = row[lane + 32 * i]; mx = fmaxf(mx, v[i]); }
    #pragma unroll
    for (int o = 16; o; o >>= 1) mx = fmaxf(mx, __shfl_xor_sync(0xffffffffu, mx, o));
    if (lane == 0) sred[w] = mx;
    __syncthreads();
    const float m = fmaxf(sred[r * 2], sred[r * 2 + 1]);
    float s = 0.f;
    #pragma unroll
    for (int i = 0; i < 8; i++) { v[i] = __expf(v[i] - m); s += v[i]; }
    #pragma unroll
    for (int o = 16; o; o >>= 1) s += __shfl_xor_sync(0xffffffffu, s, o);
    __syncthreads();
    if (lane == 0) sred[w] = s;
    __syncthreads();
    const float inv = 1.f / (sred[r * 2] + sred[r * 2 + 1]);
    #pragma unroll
    for (int i = 0; i < 8; i++) sP[r][h * 256 + lane + 32 * i] = v[i] * inv;
    __syncthreads();
    #pragma unroll
    for (int i = 0; i < 2; i++) {
        int mi = tid + 256 * i;
        float4 tv = make_float4(sP[0][mi], sP[1][mi], sP[2][mi], sP[3][mi]);
        *(float4*)&g_probT[mi * 512 + n0] = tv;
    }
}

// message = src @ probT          grid (8,16), 256 thr
__global__ void __launch_bounds__(256) k_msg(const float* __restrict__ src)
{
    gemm_mma16(src, g_probT, nullptr, g_msg, 512);
}

// h2 = relu(wa @ [x; msg] + ba)  grid (8,16), 256 thr
__global__ void __launch_bounds__(256) k_h2(
    const float* __restrict__ wa, const float* __restrict__ x,
    const float* __restrict__ ba)
{
    gemm_mma<true>(wa, x, g_msg, ba, g_h2, 512, true);
}

// y = wb @ h2 + bb               grid (8,16), 256 thr
__global__ void __launch_bounds__(256) k_y(
    const float* __restrict__ wb, const float* __restrict__ bb,
    float* __restrict__ y)
{
    gemm_mma16(wb, g_h2, bb, y, 512);
}

// ---------------- launch ----------------
extern "C" void kernel_launch(void* const* d_in, const int* in_sizes, int n_in,
                              void* d_out, int out_size)
{
    const float* x   = (const float*)d_in[0];
    const float* src = (const float*)d_in[1];
    const float* w1  = (const float*)d_in[2];
    const float* b1  = (const float*)d_in[3];
    const float* w2  = (const float*)d_in[4];
    const float* b2  = (const float*)d_in[5];
    const float* wa  = (const float*)d_in[6];
    const float* ba  = (const float*)d_in[7];
    const float* wb  = (const float*)d_in[8];
    const float* bb  = (const float*)d_in[9];

    float* y      = (float*)d_out;   // (1, D, NQ)
    float* scores = y + D * NQ;      // (1, NQ, NK)

    k_qk      <<<dim3(8, 8, 2), 256>>>(w1, x, src, b1);
    k_score   <<<dim3(8, 16),   256>>>(w2, b2, scores);
    k_softmaxT<<<128,           256>>>(scores);
    k_msg     <<<dim3(8, 16),   256>>>(src);
    k_h2      <<<dim3(8, 16),   256>>>(wa, x, ba);
    k_y       <<<dim3(8, 16),   256>>>(wb, bb, y);
}

// round 12
// speedup vs baseline: 1.1135x; 1.1135x over previous
#include <cuda_runtime.h>
#include <math.h>

#define D   256
#define NQ  512
#define NK  512

// ---------------- scratch ----------------
__device__ __align__(16) float g_aq[D * NQ];      // (d, n)
__device__ __align__(16) float g_ak[D * NK];      // (d, m)
__device__ __align__(16) float g_probT[NK * NQ];  // (m, n)
__device__ __align__(16) float g_msg[D * NQ];     // (d, n)
__device__ __align__(16) float g_h2[2 * D * NQ];  // (o, n)

// ---------------- helpers ----------------
__device__ __forceinline__ float f2tf(float f) {
    unsigned u; asm("cvt.rna.tf32.f32 %0, %1;" : "=r"(u) : "f"(f));
    return __uint_as_float(u);
}
__device__ __forceinline__ void mma_tf32(float4& c,
    float a0, float a1, float a2, float a3, float b0, float b1)
{
    asm("mma.sync.aligned.m16n8k8.row.col.f32.tf32.tf32.f32 "
        "{%0,%1,%2,%3}, {%4,%5,%6,%7}, {%8,%9}, {%0,%1,%2,%3};"
        : "+f"(c.x), "+f"(c.y), "+f"(c.z), "+f"(c.w)
        : "r"(__float_as_uint(a0)), "r"(__float_as_uint(a1)),
          "r"(__float_as_uint(a2)), "r"(__float_as_uint(a3)),
          "r"(__float_as_uint(b0)), "r"(__float_as_uint(b1)));
}
__device__ __forceinline__ unsigned s2u(const void* p) {
    return (unsigned)__cvta_generic_to_shared(p);
}
__device__ __forceinline__ void cp16(unsigned dst, const void* src) {
    asm volatile("cp.async.ca.shared.global [%0], [%1], 16;" :: "r"(dst), "l"(src));
}
#define CP_COMMIT() asm volatile("cp.async.commit_group;")
#define CP_WAIT2()  asm volatile("cp.async.wait_group 2;")

// ---------- Core A: TF32 MMA, tile 32 x 64, 256 thr, 3-stage cp.async ------
// out[o0..+31][n0..+63] = act(sum_k W[o][k]*X[k][n] + bias[o]); strides 512.
// 8 warps: warp = mt(2) x ng(4); each computes m16 x n16.
// DUAL: X rows <256 from X0, >=256 from X1.
template<bool DUAL>
__device__ __forceinline__ void gemmA(
    const float* __restrict__ W, const float* __restrict__ X0,
    const float* __restrict__ X1, const float* __restrict__ bias,
    float* __restrict__ out, int K, bool relu)
{
    const int n0   = blockIdx.x * 64;
    const int o0   = blockIdx.y * 32;
    const int tid  = threadIdx.x;
    const int warp = tid >> 5, lane = tid & 31;
    const int g    = lane >> 2, t4 = lane & 3;
    const int mt   = warp & 1;
    const int ng   = (warp >> 1) * 16;

    __shared__ __align__(16) float sW[3][32 * 36];  // [o][k], stride 36
    __shared__ __align__(16) float sX[3][32 * 72];  // [k][n], stride 72

    const int wo = tid >> 3, wf = tid & 7;          // W: 1 chunk/thread
    const int xn4 = tid & 15, xk = tid >> 4;        // X: 2 chunks/thread

    const int NIT = K >> 5;

    float4 acc[2] = {make_float4(0.f,0.f,0.f,0.f), make_float4(0.f,0.f,0.f,0.f)};

    auto issue = [&](int tile, int st) {
        const int k0 = tile * 32;
        cp16(s2u(&sW[st][wo * 36 + wf * 4]), &W[(o0 + wo) * 512 + k0 + wf * 4]);
        #pragma unroll
        for (int p = 0; p < 2; p++) {
            const int c = k0 + xk + p * 16;
            const float* src = (!DUAL || c < 256)
                ? &X0[c * 512 + n0 + xn4 * 4]
                : &X1[(c - 256) * 512 + n0 + xn4 * 4];
            cp16(s2u(&sX[st][(xk + p * 16) * 72 + xn4 * 4]), src);
        }
    };

    issue(0, 0); CP_COMMIT();
    issue(1, 1); CP_COMMIT();

    for (int it = 0; it < NIT; it++) {
        const int st = it % 3;
        if (it + 2 < NIT) issue(it + 2, (it + 2) % 3);
        CP_COMMIT();
        CP_WAIT2();
        __syncthreads();
        const int ob = mt * 16 + g;
        #pragma unroll
        for (int s = 0; s < 4; s++) {
            const int ks = s * 8;
            float a0 = f2tf(sW[st][(ob    ) * 36 + ks + t4]);
            float a1 = f2tf(sW[st][(ob + 8) * 36 + ks + t4]);
            float a2 = f2tf(sW[st][(ob    ) * 36 + ks + t4 + 4]);
            float a3 = f2tf(sW[st][(ob + 8) * 36 + ks + t4 + 4]);
            #pragma unroll
            for (int j = 0; j < 2; j++) {
                const int nc = ng + j * 8 + g;
                float b0 = f2tf(sX[st][(ks + t4    ) * 72 + nc]);
                float b1 = f2tf(sX[st][(ks + t4 + 4) * 72 + nc]);
                mma_tf32(acc[j], a0, a1, a2, a3, b0, b1);
            }
        }
        __syncthreads();
    }

    const int oA = o0 + mt * 16 + g;
    const int oB = oA + 8;
    const float bA = bias ? bias[oA] : 0.f;
    const float bB = bias ? bias[oB] : 0.f;
    #pragma unroll
    for (int j = 0; j < 2; j++) {
        float c0 = acc[j].x + bA, c1 = acc[j].y + bA;
        float c2 = acc[j].z + bB, c3 = acc[j].w + bB;
        if (relu) {
            c0 = fmaxf(c0, 0.f); c1 = fmaxf(c1, 0.f);
            c2 = fmaxf(c2, 0.f); c3 = fmaxf(c3, 0.f);
        }
        const int nc = n0 + ng + j * 8 + 2 * t4;
        *(float2*)&out[oA * 512 + nc] = make_float2(c0, c1);
        *(float2*)&out[oB * 512 + nc] = make_float2(c2, c3);
    }
}

// ---------- Core B: TF32 MMA, tile 16 x 64, 256 thr, 3-stage cp.async ------
// For 256-row outputs -> grid (8,16) = 128 blocks. 8 warps each m16 x n8.
__device__ __forceinline__ void gemmB(
    const float* __restrict__ W, const float* __restrict__ X0,
    const float* __restrict__ bias, float* __restrict__ out, int K)
{
    const int n0   = blockIdx.x * 64;
    const int o0   = blockIdx.y * 16;
    const int tid  = threadIdx.x;
    const int warp = tid >> 5, lane = tid & 31;
    const int g    = lane >> 2, t4 = lane & 3;

    __shared__ __align__(16) float sW[3][16 * 36];
    __shared__ __align__(16) float sX[3][32 * 72];

    const int wo = tid >> 3, wf = tid & 7;          // W: tid<128 only
    const int xn4 = tid & 15, xk = tid >> 4;

    const int NIT = K >> 5;

    float4 acc = make_float4(0.f, 0.f, 0.f, 0.f);

    auto issue = [&](int tile, int st) {
        const int k0 = tile * 32;
        if (tid < 128)
            cp16(s2u(&sW[st][wo * 36 + wf * 4]), &W[(o0 + wo) * 512 + k0 + wf * 4]);
        #pragma unroll
        for (int p = 0; p < 2; p++) {
            const int c = k0 + xk + p * 16;
            cp16(s2u(&sX[st][(xk + p * 16) * 72 + xn4 * 4]),
                 &X0[c * 512 + n0 + xn4 * 4]);
        }
    };

    issue(0, 0); CP_COMMIT();
    issue(1, 1); CP_COMMIT();

    for (int it = 0; it < NIT; it++) {
        const int st = it % 3;
        if (it + 2 < NIT) issue(it + 2, (it + 2) % 3);
        CP_COMMIT();
        CP_WAIT2();
        __syncthreads();
        const int nc = warp * 8 + g;
        #pragma unroll
        for (int s = 0; s < 4; s++) {
            const int ks = s * 8;
            float a0 = f2tf(sW[st][(g    ) * 36 + ks + t4]);
            float a1 = f2tf(sW[st][(g + 8) * 36 + ks + t4]);
            float a2 = f2tf(sW[st][(g    ) * 36 + ks + t4 + 4]);
            float a3 = f2tf(sW[st][(g + 8) * 36 + ks + t4 + 4]);
            float b0 = f2tf(sX[st][(ks + t4    ) * 72 + nc]);
            float b1 = f2tf(sX[st][(ks + t4 + 4) * 72 + nc]);
            mma_tf32(acc, a0, a1, a2, a3, b0, b1);
        }
        __syncthreads();
    }

    const int oA = o0 + g, oB = oA + 8;
    const float bA = bias ? bias[oA] : 0.f;
    const float bB = bias ? bias[oB] : 0.f;
    const int nc = n0 + warp * 8 + 2 * t4;
    *(float2*)&out[oA * 512 + nc] = make_float2(acc.x + bA, acc.y + bA);
    *(float2*)&out[oB * 512 + nc] = make_float2(acc.z + bB, acc.w + bB);
}

// ---------------- stage kernels ----------------

// aq = w1[:, :D] @ x + b1 ; ak = w1[:, D:] @ src   grid (8,8,2), 256 thr
__global__ void __launch_bounds__(256) k_qk(
    const float* __restrict__ w1, const float* __restrict__ x,
    const float* __restrict__ src, const float* __restrict__ b1)
{
    if (blockIdx.z == 0)
        gemmA<false>(w1,       x,   nullptr, b1,      g_aq, 256, false);
    else
        gemmA<false>(w1 + 256, src, nullptr, nullptr, g_ak, 256, false);
}

// scores[n][m] = sum_d w2[d]*relu(aq[d][n]+ak[d][m]) + b2   grid (8,16), 256 thr
__global__ void __launch_bounds__(256) k_score(
    const float* __restrict__ w2, const float* __restrict__ b2,
    float* __restrict__ scores)
{
    const int m0  = blockIdx.x * 64;
    const int n0  = blockIdx.y * 32;
    const int tid = threadIdx.x;
    const int wg  = tid >> 7;
    const int t   = tid & 127;
    const int mI  = t & 15;
    const int nG  = t >> 4;

    __shared__ __align__(16) float sA[2][32 * 36];
    __shared__ __align__(16) float sB[2][32 * 68];
    __shared__ float sw[2][32];
    __shared__ __align__(16) float sR[128 * 16];

    const int an4 = t & 7,  adr = t >> 3;
    const int bm4 = t & 15, bdr = t >> 4;
    const int db  = wg * 128;

    float4 ra[2], rb[4];
    float rwv;
    float4 acc[4];
    #pragma unroll
    for (int j = 0; j < 4; j++) acc[j] = make_float4(0.f, 0.f, 0.f, 0.f);

    #pragma unroll
    for (int p = 0; p < 2; p++)
        ra[p] = *(const float4*)&g_aq[(db + adr + p * 16) * 512 + n0 + an4 * 4];
    #pragma unroll
    for (int p = 0; p < 4; p++)
        rb[p] = *(const float4*)&g_ak[(db + bdr + p * 8) * 512 + m0 + bm4 * 4];
    rwv = (t < 32) ? w2[db + t] : 0.f;

    for (int it = 0; it < 4; it++) {
        __syncthreads();
        #pragma unroll
        for (int p = 0; p < 2; p++)
            *(float4*)&sA[wg][(adr + p * 16) * 36 + an4 * 4] = ra[p];
        #pragma unroll
        for (int p = 0; p < 4; p++)
            *(float4*)&sB[wg][(bdr + p * 8) * 68 + bm4 * 4] = rb[p];
        if (t < 32) sw[wg][t] = rwv;
        __syncthreads();

        if (it + 1 < 4) {
            const int d0 = db + (it + 1) * 32;
            #pragma unroll
            for (int p = 0; p < 2; p++)
                ra[p] = *(const float4*)&g_aq[(d0 + adr + p * 16) * 512 + n0 + an4 * 4];
            #pragma unroll
            for (int p = 0; p < 4; p++)
                rb[p] = *(const float4*)&g_ak[(d0 + bdr + p * 8) * 512 + m0 + bm4 * 4];
            if (t < 32) rwv = w2[d0 + t];
        }

        #pragma unroll
        for (int d = 0; d < 32; d++) {
            float4 av = *(const float4*)&sA[wg][d * 36 + nG * 4];
            float4 bv = *(const float4*)&sB[wg][d * 68 + mI * 4];
            float w  = sw[wg][d];
            float a[4] = {av.x, av.y, av.z, av.w};
            #pragma unroll
            for (int j = 0; j < 4; j++) {
                acc[j].x += w * fmaxf(a[j] + bv.x, 0.f);
                acc[j].y += w * fmaxf(a[j] + bv.y, 0.f);
                acc[j].z += w * fmaxf(a[j] + bv.z, 0.f);
                acc[j].w += w * fmaxf(a[j] + bv.w, 0.f);
            }
        }
    }

    if (wg == 1) {
        #pragma unroll
        for (int j = 0; j < 4; j++)
            *(float4*)&sR[(t * 4 + j) * 4] = acc[j];
    }
    __syncthreads();
    if (wg == 0) {
        const float bs = b2[0];
        #pragma unroll
        for (int j = 0; j < 4; j++) {
            float4 r = *(const float4*)&sR[(t * 4 + j) * 4];
            const int n = n0 + nG * 4 + j;
            float4 v = acc[j];
            v.x += r.x + bs; v.y += r.y + bs;
            v.z += r.z + bs; v.w += r.w + bs;
            *(float4*)&scores[n * 512 + m0 + mI * 4] = v;
        }
    }
}

// softmax over m per row n -> transposed prob. 128 blocks x 256 thr.
__global__ void __launch_bounds__(256) k_softmaxT(const float* __restrict__ scores)
{
    const int n0   = blockIdx.x * 4;
    const int tid  = threadIdx.x;
    const int w    = tid >> 5, lane = tid & 31;
    const int r    = w >> 1, h = w & 1;
    __shared__ float sP[4][516];
    __shared__ float sred[8];

    const float* row = scores + (n0 + r) * 512 + h * 256;
    float v[8];
    float mx = -1e30f;
    #pragma unroll
    for (int i = 0; i < 8; i++) { v[i] = row[lane + 32 * i]; mx = fmaxf(mx, v[i]); }
    #pragma unroll
    for (int o = 16; o; o >>= 1) mx = fmaxf(mx, __shfl_xor_sync(0xffffffffu, mx, o));
    if (lane == 0) sred[w] = mx;
    __syncthreads();
    const float m = fmaxf(sred[r * 2], sred[r * 2 + 1]);
    float s = 0.f;
    #pragma unroll
    for (int i = 0; i < 8; i++) { v[i] = __expf(v[i] - m); s += v[i]; }
    #pragma unroll
    for (int o = 16; o; o >>= 1) s += __shfl_xor_sync(0xffffffffu, s, o);
    __syncthreads();
    if (lane == 0) sred[w] = s;
    __syncthreads();
    const float inv = 1.f / (sred[r * 2] + sred[r * 2 + 1]);
    #pragma unroll
    for (int i = 0; i < 8; i++) sP[r][h * 256 + lane + 32 * i] = v[i] * inv;
    __syncthreads();
    #pragma unroll
    for (int i = 0; i < 2; i++) {
        int mi = tid + 256 * i;
        float4 tv = make_float4(sP[0][mi], sP[1][mi], sP[2][mi], sP[3][mi]);
        *(float4*)&g_probT[mi * 512 + n0] = tv;
    }
}

// message = src @ probT          grid (8,16), 256 thr
__global__ void __launch_bounds__(256) k_msg(const float* __restrict__ src)
{
    gemmB(src, g_probT, nullptr, g_msg, 512);
}

// h2 = relu(wa @ [x; msg] + ba)  grid (8,16), 256 thr
__global__ void __launch_bounds__(256) k_h2(
    const float* __restrict__ wa, const float* __restrict__ x,
    const float* __restrict__ ba)
{
    gemmA<true>(wa, x, g_msg, ba, g_h2, 512, true);
}

// y = wb @ h2 + bb               grid (8,16), 256 thr
__global__ void __launch_bounds__(256) k_y(
    const float* __restrict__ wb, const float* __restrict__ bb,
    float* __restrict__ y)
{
    gemmB(wb, g_h2, bb, y, 512);
}

// ---------------- launch ----------------
extern "C" void kernel_launch(void* const* d_in, const int* in_sizes, int n_in,
                              void* d_out, int out_size)
{
    const float* x   = (const float*)d_in[0];
    const float* src = (const float*)d_in[1];
    const float* w1  = (const float*)d_in[2];
    const float* b1  = (const float*)d_in[3];
    const float* w2  = (const float*)d_in[4];
    const float* b2  = (const float*)d_in[5];
    const float* wa  = (const float*)d_in[6];
    const float* ba  = (const float*)d_in[7];
    const float* wb  = (const float*)d_in[8];
    const float* bb  = (const float*)d_in[9];

    float* y      = (float*)d_out;   // (1, D, NQ)
    float* scores = y + D * NQ;      // (1, NQ, NK)

    k_qk      <<<dim3(8, 8, 2), 256>>>(w1, x, src, b1);
    k_score   <<<dim3(8, 16),   256>>>(w2, b2, scores);
    k_softmaxT<<<128,           256>>>(scores);
    k_msg     <<<dim3(8, 16),   256>>>(src);
    k_h2      <<<dim3(8, 16),   256>>>(wa, x, ba);
    k_y       <<<dim3(8, 16),   256>>>(wb, bb, y);
}

// round 13
// speedup vs baseline: 1.2271x; 1.1020x over previous
#include <cuda_runtime.h>
#include <math.h>

#define D   256
#define NQ  512
#define NK  512

// ---------------- scratch ----------------
__device__ __align__(16) float g_aq[D * NQ];      // (d, n)  full f32 (score input)
__device__ __align__(16) float g_ak[D * NK];      // (d, m)  full f32
__device__ __align__(16) float g_probT[NK * NQ];  // (m, n)  tf32-rounded
__device__ __align__(16) float g_msg[D * NQ];     // (d, n)  tf32-rounded
__device__ __align__(16) float g_h2[2 * D * NQ];  // (o, n)  tf32-rounded

// tf32-rounded copies of input operand tensors
__device__ __align__(16) float g_w1t[D * 2 * D];   // 256x512
__device__ __align__(16) float g_xt [D * NQ];      // 256x512
__device__ __align__(16) float g_srct[D * NK];     // 256x512
__device__ __align__(16) float g_wat[2 * D * 2 * D]; // 512x512
__device__ __align__(16) float g_wbt[D * 2 * D];   // 256x512

// ---------------- helpers ----------------
__device__ __forceinline__ float f2tf(float f) {
    unsigned u; asm("cvt.rna.tf32.f32 %0, %1;" : "=r"(u) : "f"(f));
    return __uint_as_float(u);
}
__device__ __forceinline__ void mma_tf32(float4& c,
    float a0, float a1, float a2, float a3, float b0, float b1)
{
    asm("mma.sync.aligned.m16n8k8.row.col.f32.tf32.tf32.f32 "
        "{%0,%1,%2,%3}, {%4,%5,%6,%7}, {%8,%9}, {%0,%1,%2,%3};"
        : "+f"(c.x), "+f"(c.y), "+f"(c.z), "+f"(c.w)
        : "r"(__float_as_uint(a0)), "r"(__float_as_uint(a1)),
          "r"(__float_as_uint(a2)), "r"(__float_as_uint(a3)),
          "r"(__float_as_uint(b0)), "r"(__float_as_uint(b1)));
}
__device__ __forceinline__ unsigned s2u(const void* p) {
    return (unsigned)__cvta_generic_to_shared(p);
}
__device__ __forceinline__ void cp16(unsigned dst, const void* src) {
    asm volatile("cp.async.ca.shared.global [%0], [%1], 16;" :: "r"(dst), "l"(src));
}
#define CP_COMMIT() asm volatile("cp.async.commit_group;")
#define CP_WAIT2()  asm volatile("cp.async.wait_group 2;")

// ---------------- pre-convert inputs to tf32 bits ----------------
// 768 blocks x 256 thr, one float4 per thread.
__global__ void __launch_bounds__(256) k_cvt(
    const float* __restrict__ x, const float* __restrict__ src,
    const float* __restrict__ w1, const float* __restrict__ wa,
    const float* __restrict__ wb)
{
    const int b = blockIdx.x;
    const float* s; float* d; int off;
    if      (b < 128) { s = w1;  d = g_w1t;  off = b; }
    else if (b < 256) { s = x;   d = g_xt;   off = b - 128; }
    else if (b < 384) { s = src; d = g_srct; off = b - 256; }
    else if (b < 640) { s = wa;  d = g_wat;  off = b - 384; }
    else              { s = wb;  d = g_wbt;  off = b - 640; }
    const int i = off * 256 + threadIdx.x;
    float4 v = ((const float4*)s)[i];
    v.x = f2tf(v.x); v.y = f2tf(v.y); v.z = f2tf(v.z); v.w = f2tf(v.w);
    ((float4*)d)[i] = v;
}

// ---------- Core A: TF32 MMA, tile 32 x 64, 256 thr, 3-stage cp.async ------
// Operands already tf32-rounded. 8 warps, each m16 x n16. Strides 512.
// DUAL: X rows <256 from X0, >=256 from X1. ROUND: round outputs to tf32.
template<bool DUAL, bool ROUND>
__device__ __forceinline__ void gemmA(
    const float* __restrict__ W, const float* __restrict__ X0,
    const float* __restrict__ X1, const float* __restrict__ bias,
    float* __restrict__ out, int K, bool relu)
{
    const int n0   = blockIdx.x * 64;
    const int o0   = blockIdx.y * 32;
    const int tid  = threadIdx.x;
    const int warp = tid >> 5, lane = tid & 31;
    const int g    = lane >> 2, t4 = lane & 3;
    const int mt   = warp & 1;
    const int ng   = (warp >> 1) * 16;

    __shared__ __align__(16) float sW[3][32 * 36];  // [o][k]
    __shared__ __align__(16) float sX[3][32 * 72];  // [k][n]

    const int wo = tid >> 3, wf = tid & 7;
    const int xn4 = tid & 15, xk = tid >> 4;

    const int NIT = K >> 5;

    float4 acc[2] = {make_float4(0.f,0.f,0.f,0.f), make_float4(0.f,0.f,0.f,0.f)};

    auto issue = [&](int tile, int st) {
        const int k0 = tile * 32;
        cp16(s2u(&sW[st][wo * 36 + wf * 4]), &W[(o0 + wo) * 512 + k0 + wf * 4]);
        #pragma unroll
        for (int p = 0; p < 2; p++) {
            const int c = k0 + xk + p * 16;
            const float* src = (!DUAL || c < 256)
                ? &X0[c * 512 + n0 + xn4 * 4]
                : &X1[(c - 256) * 512 + n0 + xn4 * 4];
            cp16(s2u(&sX[st][(xk + p * 16) * 72 + xn4 * 4]), src);
        }
    };

    issue(0, 0); CP_COMMIT();
    issue(1, 1); CP_COMMIT();

    for (int it = 0; it < NIT; it++) {
        const int st = it % 3;
        if (it + 2 < NIT) issue(it + 2, (it + 2) % 3);
        CP_COMMIT();
        CP_WAIT2();
        __syncthreads();
        const int ob = mt * 16 + g;
        #pragma unroll
        for (int s = 0; s < 4; s++) {
            const int ks = s * 8;
            float a0 = sW[st][(ob    ) * 36 + ks + t4];
            float a1 = sW[st][(ob + 8) * 36 + ks + t4];
            float a2 = sW[st][(ob    ) * 36 + ks + t4 + 4];
            float a3 = sW[st][(ob + 8) * 36 + ks + t4 + 4];
            #pragma unroll
            for (int j = 0; j < 2; j++) {
                const int nc = ng + j * 8 + g;
                float b0 = sX[st][(ks + t4    ) * 72 + nc];
                float b1 = sX[st][(ks + t4 + 4) * 72 + nc];
                mma_tf32(acc[j], a0, a1, a2, a3, b0, b1);
            }
        }
        __syncthreads();
    }

    const int oA = o0 + mt * 16 + g;
    const int oB = oA + 8;
    const float bA = bias ? bias[oA] : 0.f;
    const float bB = bias ? bias[oB] : 0.f;
    #pragma unroll
    for (int j = 0; j < 2; j++) {
        float c0 = acc[j].x + bA, c1 = acc[j].y + bA;
        float c2 = acc[j].z + bB, c3 = acc[j].w + bB;
        if (relu) {
            c0 = fmaxf(c0, 0.f); c1 = fmaxf(c1, 0.f);
            c2 = fmaxf(c2, 0.f); c3 = fmaxf(c3, 0.f);
        }
        if (ROUND) {
            c0 = f2tf(c0); c1 = f2tf(c1); c2 = f2tf(c2); c3 = f2tf(c3);
        }
        const int nc = n0 + ng + j * 8 + 2 * t4;
        *(float2*)&out[oA * 512 + nc] = make_float2(c0, c1);
        *(float2*)&out[oB * 512 + nc] = make_float2(c2, c3);
    }
}

// ---------- Core B: TF32 MMA, tile 16 x 64, 256 thr, 3-stage cp.async ------
// 8 warps each m16 x n8. Operands pre-rounded.
template<bool ROUND>
__device__ __forceinline__ void gemmB(
    const float* __restrict__ W, const float* __restrict__ X0,
    const float* __restrict__ bias, float* __restrict__ out, int K)
{
    const int n0   = blockIdx.x * 64;
    const int o0   = blockIdx.y * 16;
    const int tid  = threadIdx.x;
    const int warp = tid >> 5, lane = tid & 31;
    const int g    = lane >> 2, t4 = lane & 3;

    __shared__ __align__(16) float sW[3][16 * 36];
    __shared__ __align__(16) float sX[3][32 * 72];

    const int wo = tid >> 3, wf = tid & 7;          // W: tid<128 only
    const int xn4 = tid & 15, xk = tid >> 4;

    const int NIT = K >> 5;

    float4 acc = make_float4(0.f, 0.f, 0.f, 0.f);

    auto issue = [&](int tile, int st) {
        const int k0 = tile * 32;
        if (tid < 128)
            cp16(s2u(&sW[st][wo * 36 + wf * 4]), &W[(o0 + wo) * 512 + k0 + wf * 4]);
        #pragma unroll
        for (int p = 0; p < 2; p++) {
            const int c = k0 + xk + p * 16;
            cp16(s2u(&sX[st][(xk + p * 16) * 72 + xn4 * 4]),
                 &X0[c * 512 + n0 + xn4 * 4]);
        }
    };

    issue(0, 0); CP_COMMIT();
    issue(1, 1); CP_COMMIT();

    for (int it = 0; it < NIT; it++) {
        const int st = it % 3;
        if (it + 2 < NIT) issue(it + 2, (it + 2) % 3);
        CP_COMMIT();
        CP_WAIT2();
        __syncthreads();
        const int nc = warp * 8 + g;
        #pragma unroll
        for (int s = 0; s < 4; s++) {
            const int ks = s * 8;
            float a0 = sW[st][(g    ) * 36 + ks + t4];
            float a1 = sW[st][(g + 8) * 36 + ks + t4];
            float a2 = sW[st][(g    ) * 36 + ks + t4 + 4];
            float a3 = sW[st][(g + 8) * 36 + ks + t4 + 4];
            float b0 = sX[st][(ks + t4    ) * 72 + nc];
            float b1 = sX[st][(ks + t4 + 4) * 72 + nc];
            mma_tf32(acc, a0, a1, a2, a3, b0, b1);
        }
        __syncthreads();
    }

    const int oA = o0 + g, oB = oA + 8;
    const float bA = bias ? bias[oA] : 0.f;
    const float bB = bias ? bias[oB] : 0.f;
    float c0 = acc.x + bA, c1 = acc.y + bA;
    float c2 = acc.z + bB, c3 = acc.w + bB;
    if (ROUND) { c0 = f2tf(c0); c1 = f2tf(c1); c2 = f2tf(c2); c3 = f2tf(c3); }
    const int nc = n0 + warp * 8 + 2 * t4;
    *(float2*)&out[oA * 512 + nc] = make_float2(c0, c1);
    *(float2*)&out[oB * 512 + nc] = make_float2(c2, c3);
}

// ---------------- stage kernels ----------------

// aq = w1[:, :D] @ x + b1 ; ak = w1[:, D:] @ src   grid (8,8,2), 256 thr
// outputs stay full f32 (consumed by SIMT score kernel only)
__global__ void __launch_bounds__(256) k_qk(const float* __restrict__ b1)
{
    if (blockIdx.z == 0)
        gemmA<false, false>(g_w1t,       g_xt,   nullptr, b1,      g_aq, 256, false);
    else
        gemmA<false, false>(g_w1t + 256, g_srct, nullptr, nullptr, g_ak, 256, false);
}

// scores[n][m] = sum_d w2[d]*relu(aq[d][n]+ak[d][m]) + b2   grid (8,16), 256 thr
__global__ void __launch_bounds__(256) k_score(
    const float* __restrict__ w2, const float* __restrict__ b2,
    float* __restrict__ scores)
{
    const int m0  = blockIdx.x * 64;
    const int n0  = blockIdx.y * 32;
    const int tid = threadIdx.x;
    const int wg  = tid >> 7;
    const int t   = tid & 127;
    const int mI  = t & 15;
    const int nG  = t >> 4;

    __shared__ __align__(16) float sA[2][32 * 36];
    __shared__ __align__(16) float sB[2][32 * 68];
    __shared__ float sw[2][32];
    __shared__ __align__(16) float sR[128 * 16];

    const int an4 = t & 7,  adr = t >> 3;
    const int bm4 = t & 15, bdr = t >> 4;
    const int db  = wg * 128;

    float4 ra[2], rb[4];
    float rwv;
    float4 acc[4];
    #pragma unroll
    for (int j = 0; j < 4; j++) acc[j] = make_float4(0.f, 0.f, 0.f, 0.f);

    #pragma unroll
    for (int p = 0; p < 2; p++)
        ra[p] = *(const float4*)&g_aq[(db + adr + p * 16) * 512 + n0 + an4 * 4];
    #pragma unroll
    for (int p = 0; p < 4; p++)
        rb[p] = *(const float4*)&g_ak[(db + bdr + p * 8) * 512 + m0 + bm4 * 4];
    rwv = (t < 32) ? w2[db + t] : 0.f;

    for (int it = 0; it < 4; it++) {
        __syncthreads();
        #pragma unroll
        for (int p = 0; p < 2; p++)
            *(float4*)&sA[wg][(adr + p * 16) * 36 + an4 * 4] = ra[p];
        #pragma unroll
        for (int p = 0; p < 4; p++)
            *(float4*)&sB[wg][(bdr + p * 8) * 68 + bm4 * 4] = rb[p];
        if (t < 32) sw[wg][t] = rwv;
        __syncthreads();

        if (it + 1 < 4) {
            const int d0 = db + (it + 1) * 32;
            #pragma unroll
            for (int p = 0; p < 2; p++)
                ra[p] = *(const float4*)&g_aq[(d0 + adr + p * 16) * 512 + n0 + an4 * 4];
            #pragma unroll
            for (int p = 0; p < 4; p++)
                rb[p] = *(const float4*)&g_ak[(d0 + bdr + p * 8) * 512 + m0 + bm4 * 4];
            if (t < 32) rwv = w2[d0 + t];
        }

        #pragma unroll
        for (int d = 0; d < 32; d++) {
            float4 av = *(const float4*)&sA[wg][d * 36 + nG * 4];
            float4 bv = *(const float4*)&sB[wg][d * 68 + mI * 4];
            float w  = sw[wg][d];
            float a[4] = {av.x, av.y, av.z, av.w};
            #pragma unroll
            for (int j = 0; j < 4; j++) {
                acc[j].x += w * fmaxf(a[j] + bv.x, 0.f);
                acc[j].y += w * fmaxf(a[j] + bv.y, 0.f);
                acc[j].z += w * fmaxf(a[j] + bv.z, 0.f);
                acc[j].w += w * fmaxf(a[j] + bv.w, 0.f);
            }
        }
    }

    if (wg == 1) {
        #pragma unroll
        for (int j = 0; j < 4; j++)
            *(float4*)&sR[(t * 4 + j) * 4] = acc[j];
    }
    __syncthreads();
    if (wg == 0) {
        const float bs = b2[0];
        #pragma unroll
        for (int j = 0; j < 4; j++) {
            float4 r = *(const float4*)&sR[(t * 4 + j) * 4];
            const int n = n0 + nG * 4 + j;
            float4 v = acc[j];
            v.x += r.x + bs; v.y += r.y + bs;
            v.z += r.z + bs; v.w += r.w + bs;
            *(float4*)&scores[n * 512 + m0 + mI * 4] = v;
        }
    }
}

// softmax over m per row n -> transposed prob (tf32-rounded). 128 x 256 thr.
__global__ void __launch_bounds__(256) k_softmaxT(const float* __restrict__ scores)
{
    const int n0   = blockIdx.x * 4;
    const int tid  = threadIdx.x;
    const int w    = tid >> 5, lane = tid & 31;
    const int r    = w >> 1, h = w & 1;
    __shared__ float sP[4][516];
    __shared__ float sred[8];

    const float* row = scores + (n0 + r) * 512 + h * 256;
    float v[8];
    float mx = -1e30f;
    #pragma unroll
    for (int i = 0; i < 8; i++) { v[i] = row[lane + 32 * i]; mx = fmaxf(mx, v[i]); }
    #pragma unroll
    for (int o = 16; o; o >>= 1) mx = fmaxf(mx, __shfl_xor_sync(0xffffffffu, mx, o));
    if (lane == 0) sred[w] = mx;
    __syncthreads();
    const float m = fmaxf(sred[r * 2], sred[r * 2 + 1]);
    float s = 0.f;
    #pragma unroll
    for (int i = 0; i < 8; i++) { v[i] = __expf(v[i] - m); s += v[i]; }
    #pragma unroll
    for (int o = 16; o; o >>= 1) s += __shfl_xor_sync(0xffffffffu, s, o);
    __syncthreads();
    if (lane == 0) sred[w] = s;
    __syncthreads();
    const float inv = 1.f / (sred[r * 2] + sred[r * 2 + 1]);
    #pragma unroll
    for (int i = 0; i < 8; i++) sP[r][h * 256 + lane + 32 * i] = v[i] * inv;
    __syncthreads();
    #pragma unroll
    for (int i = 0; i < 2; i++) {
        int mi = tid + 256 * i;
        float4 tv = make_float4(f2tf(sP[0][mi]), f2tf(sP[1][mi]),
                                f2tf(sP[2][mi]), f2tf(sP[3][mi]));
        *(float4*)&g_probT[mi * 512 + n0] = tv;
    }
}

// message = src @ probT          grid (8,16), 256 thr   (output rounded)
__global__ void __launch_bounds__(256) k_msg()
{
    gemmB<true>(g_srct, g_probT, nullptr, g_msg, 512);
}

// h2 = relu(wa @ [x; msg] + ba)  grid (8,16), 256 thr   (output rounded)
__global__ void __launch_bounds__(256) k_h2(const float* __restrict__ ba)
{
    gemmA<true, true>(g_wat, g_xt, g_msg, ba, g_h2, 512, true);
}

// y = wb @ h2 + bb               grid (8,16), 256 thr   (output full f32)
__global__ void __launch_bounds__(256) k_y(
    const float* __restrict__ bb, float* __restrict__ y)
{
    gemmB<false>(g_wbt, g_h2, bb, y, 512);
}

// ---------------- launch ----------------
extern "C" void kernel_launch(void* const* d_in, const int* in_sizes, int n_in,
                              void* d_out, int out_size)
{
    const float* x   = (const float*)d_in[0];
    const float* src = (const float*)d_in[1];
    const float* w1  = (const float*)d_in[2];
    const float* b1  = (const float*)d_in[3];
    const float* w2  = (const float*)d_in[4];
    const float* b2  = (const float*)d_in[5];
    const float* wa  = (const float*)d_in[6];
    const float* ba  = (const float*)d_in[7];
    const float* wb  = (const float*)d_in[8];
    const float* bb  = (const float*)d_in[9];

    float* y      = (float*)d_out;   // (1, D, NQ)
    float* scores = y + D * NQ;      // (1, NQ, NK)

    k_cvt     <<<768,           256>>>(x, src, w1, wa, wb);
    k_qk      <<<dim3(8, 8, 2), 256>>>(b1);
    k_score   <<<dim3(8, 16),   256>>>(w2, b2, scores);
    k_softmaxT<<<128,           256>>>(scores);
    k_msg     <<<dim3(8, 16),   256>>>();
    k_h2      <<<dim3(8, 16),   256>>>(ba);
    k_y       <<<dim3(8, 16),   256>>>(bb, y);
}